// round 1
// baseline (speedup 1.0000x reference)
#include <cuda_runtime.h>

// Problem constants (fixed by the dataset)
#define NN      262144            // nodes per tree (2^18)
#define NT      12                // B*C trees
#define HWPX    1048576           // H*W (2^20)
#define PREFIX  2048              // exactly-solved low-index prefix per tree (2^11)
#define TOTAL   (NT * NN)
#define NPIX    (NT * HWPX)

// Scratch (allocation-free rule: __device__ globals)
// g_node: packed {contrib0, contrib1, contrib2, parent-as-float-bits}
__device__ float4 g_node[TOTAL];
// g_F: final per-node filtered values {f0,f1,f2,_}
__device__ float4 g_F[TOTAL];
// g_f0: exact prefix solution for nodes [0,PREFIX) of each tree
__device__ float4 g_f0[NT * PREFIX];

__device__ __forceinline__ float sigmoidf_(float x) {
    return 1.0f / (1.0f + expf(-x));
}

// ---------------------------------------------------------------------------
// Kernel A: per-node scores -> contrib, packed with parent pointer (16B/node)
// ---------------------------------------------------------------------------
__global__ void k_contrib(const float* __restrict__ attrs,
                          const float* __restrict__ residue,
                          const float* __restrict__ W0,
                          const float* __restrict__ W1,
                          const float* __restrict__ W2,
                          const float* __restrict__ b0,
                          const float* __restrict__ b1,
                          const float* __restrict__ b2,
                          const int*   __restrict__ parent) {
    int i = blockIdx.x * blockDim.x + threadIdx.x;
    if (i >= TOTAL) return;

    float a0 = attrs[3 * i + 0];
    float a1 = attrs[3 * i + 1];
    float a2 = attrs[3 * i + 2];
    float r  = residue[i];

    float w0  = __ldg(W0);
    float w10 = __ldg(&W1[0]);
    float w11 = __ldg(&W1[1]);
    float w2  = __ldg(W2);

    float x0 = fmaf(a0, w0, __ldg(b0));
    float x1 = fmaf(a2, w11, fmaf(a1, w10, __ldg(b1)));
    float x2 = fmaf(a1, w2, __ldg(b2));

    float c0 = sigmoidf_(x0) * r;
    float c1 = sigmoidf_(x1) * r;
    float c2 = sigmoidf_(x2) * r;

    g_node[i] = make_float4(c0, c1, c2, __int_as_float(parent[i]));
}

// ---------------------------------------------------------------------------
// Kernel B: exact prefix solve for nodes [0,PREFIX) per tree.
// In-smem Wyllie pointer jumping: 11 rounds cover any chain <= 2048.
// Node 0's parent is the sentinel NN (>= PREFIX) -> naturally frozen.
// ---------------------------------------------------------------------------
__global__ void __launch_bounds__(1024, 1) k_prefix() {
    __shared__ float4 sm[PREFIX];
    const int tree = blockIdx.x;
    const float4* nb = g_node + (size_t)tree * NN;

    for (int i = threadIdx.x; i < PREFIX; i += blockDim.x)
        sm[i] = nb[i];
    __syncthreads();

    const int e0 = threadIdx.x;
    const int e1 = threadIdx.x + 1024;

    for (int r = 0; r < 11; r++) {
        float4 v0 = sm[e0];
        float4 v1 = sm[e1];
        int p0 = __float_as_int(v0.w);
        int p1 = __float_as_int(v1.w);
        if (p0 < PREFIX) {
            float4 o = sm[p0];
            v0.x += o.x; v0.y += o.y; v0.z += o.z; v0.w = o.w;
        }
        if (p1 < PREFIX) {
            float4 o = sm[p1];
            v1.x += o.x; v1.y += o.y; v1.z += o.z; v1.w = o.w;
        }
        __syncthreads();
        sm[e0] = v0;
        sm[e1] = v1;
        __syncthreads();
    }

    for (int i = threadIdx.x; i < PREFIX; i += blockDim.x)
        g_f0[tree * PREFIX + i] = sm[i];
}

// ---------------------------------------------------------------------------
// Kernel C: direct ancestor walk for nodes >= PREFIX.
// Ancestor index decays ~e^-k, so avg hops = ln(NN/PREFIX)-1 ~= 3.85,
// and chains converge into cache-hot low indices. Exact termination.
// ---------------------------------------------------------------------------
__global__ void k_walk() {
    int i = blockIdx.x * blockDim.x + threadIdx.x;
    if (i >= TOTAL) return;

    const int n    = i & (NN - 1);
    const int tree = i >> 18;

    if (n < PREFIX) {
        g_F[i] = g_f0[tree * PREFIX + n];
        return;
    }

    const float4* nb = g_node + (size_t)tree * NN;
    float4 v = nb[n];
    float ax = v.x, ay = v.y, az = v.z;
    int p = __float_as_int(v.w);

    // For n >= 1, parent is always a real node (< n), so no sentinel check.
    while (p >= PREFIX) {
        float4 u = __ldg(&nb[p]);
        ax += u.x; ay += u.y; az += u.z;
        p = __float_as_int(u.w);
    }
    float4 f = __ldg(&g_f0[tree * PREFIX + p]);
    g_F[i] = make_float4(ax + f.x, ay + f.y, az + f.z, 0.0f);
}

// ---------------------------------------------------------------------------
// Kernel D: pixel gather. One 16B gather serves all 3 output channels.
// out[((tree)*3 + g)*HW + p] = F_g[tree, pixel_node[tree, p]]
// ---------------------------------------------------------------------------
__global__ void k_gather(const int* __restrict__ pix,
                         float* __restrict__ out) {
    int q = blockIdx.x * blockDim.x + threadIdx.x;
    if (q >= NPIX) return;

    const int tree = q >> 20;          // HWPX = 2^20
    const int p    = q & (HWPX - 1);
    const int node = pix[q];

    float4 F = __ldg(&g_F[(size_t)tree * NN + node]);

    float* o = out + (size_t)tree * 3 * HWPX + p;
    o[0]          = F.x;
    o[HWPX]       = F.y;
    o[2 * HWPX]   = F.z;
}

// ---------------------------------------------------------------------------
// Entry point
// Inputs: attrs, residue, W0, W1, W2, b0, b1, b2, parent, pixel_node
// ---------------------------------------------------------------------------
extern "C" void kernel_launch(void* const* d_in, const int* in_sizes, int n_in,
                              void* d_out, int out_size) {
    const float* attrs   = (const float*)d_in[0];
    const float* residue = (const float*)d_in[1];
    const float* W0      = (const float*)d_in[2];
    const float* W1      = (const float*)d_in[3];
    const float* W2      = (const float*)d_in[4];
    const float* b0      = (const float*)d_in[5];
    const float* b1      = (const float*)d_in[6];
    const float* b2      = (const float*)d_in[7];
    const int*   parent  = (const int*)d_in[8];
    const int*   pix     = (const int*)d_in[9];
    float*       out     = (float*)d_out;

    {
        int threads = 256;
        int blocks = (TOTAL + threads - 1) / threads;
        k_contrib<<<blocks, threads>>>(attrs, residue, W0, W1, W2, b0, b1, b2, parent);
    }
    k_prefix<<<NT, 1024>>>();
    {
        int threads = 256;
        int blocks = (TOTAL + threads - 1) / threads;
        k_walk<<<blocks, threads>>>();
    }
    {
        int threads = 256;
        int blocks = (NPIX + threads - 1) / threads;
        k_gather<<<blocks, threads>>>(pix, out);
    }
}

// round 2
// speedup vs baseline: 1.2478x; 1.2478x over previous
#include <cuda_runtime.h>

// Problem constants (fixed by the dataset)
#define NN      262144            // nodes per tree (2^18)
#define NT      12                // B*C trees
#define HWPX    1048576           // H*W (2^20)
#define T0      2048              // exactly-solved prefix per tree (2^11)
#define TOTAL   (NT * NN)
#define NPIX    (NT * HWPX)

// Scratch (allocation-free rule: __device__ globals)
// g_node: packed {contrib0, contrib1, contrib2, parent-as-float-bits}
__device__ float4 g_node[TOTAL];
// g_F: final per-node filtered values {f0,f1,f2,_}
__device__ float4 g_F[TOTAL];

__device__ __forceinline__ float sigmoidf_(float x) {
    return 1.0f / (1.0f + expf(-x));
}

// ---------------------------------------------------------------------------
// Kernel A: per-node scores -> contrib, packed with parent pointer.
// 4 nodes per thread, vectorized loads/stores.
// ---------------------------------------------------------------------------
__global__ void k_contrib(const float4* __restrict__ attrs4,   // 3 float4 per 4 nodes
                          const float4* __restrict__ residue4,
                          const float* __restrict__ W0,
                          const float* __restrict__ W1,
                          const float* __restrict__ W2,
                          const float* __restrict__ b0,
                          const float* __restrict__ b1,
                          const float* __restrict__ b2,
                          const int4*  __restrict__ parent4) {
    int t = blockIdx.x * blockDim.x + threadIdx.x;
    if (t >= TOTAL / 4) return;

    float4 A0 = attrs4[3 * t + 0];   // a0[0] a1[0] a2[0] a0[1]
    float4 A1 = attrs4[3 * t + 1];   // a1[1] a2[1] a0[2] a1[2]
    float4 A2 = attrs4[3 * t + 2];   // a2[2] a0[3] a1[3] a2[3]
    float4 R  = residue4[t];
    int4   P  = parent4[t];

    const float w0  = __ldg(W0);
    const float w10 = __ldg(&W1[0]);
    const float w11 = __ldg(&W1[1]);
    const float w2  = __ldg(W2);
    const float B0 = __ldg(b0), B1 = __ldg(b1), B2 = __ldg(b2);

    float a0[4] = {A0.x, A0.w, A1.z, A2.y};
    float a1[4] = {A0.y, A1.x, A1.w, A2.z};
    float a2[4] = {A0.z, A1.y, A2.x, A2.w};
    float r[4]  = {R.x, R.y, R.z, R.w};
    int   p[4]  = {P.x, P.y, P.z, P.w};

    float4* outp = g_node + 4 * (size_t)t;
#pragma unroll
    for (int k = 0; k < 4; k++) {
        float c0 = sigmoidf_(fmaf(a0[k], w0, B0)) * r[k];
        float c1 = sigmoidf_(fmaf(a2[k], w11, fmaf(a1[k], w10, B1))) * r[k];
        float c2 = sigmoidf_(fmaf(a1[k], w2, B2)) * r[k];
        outp[k] = make_float4(c0, c1, c2, __int_as_float(p[k]));
    }
}

// ---------------------------------------------------------------------------
// Kernel B: exact prefix solve for nodes [0,T0) per tree, written to g_F.
// In-smem Wyllie pointer jumping: 11 rounds cover any chain <= 2048.
// Node 0's parent is the sentinel NN (>= T0) -> naturally frozen.
// ---------------------------------------------------------------------------
__global__ void __launch_bounds__(1024, 1) k_prefix() {
    __shared__ float4 sm[T0];
    const int tree = blockIdx.x;
    const float4* nb = g_node + (size_t)tree * NN;

    for (int i = threadIdx.x; i < T0; i += blockDim.x)
        sm[i] = nb[i];
    __syncthreads();

    const int e0 = threadIdx.x;
    const int e1 = threadIdx.x + 1024;

    for (int r = 0; r < 11; r++) {
        float4 v0 = sm[e0];
        float4 v1 = sm[e1];
        int p0 = __float_as_int(v0.w);
        int p1 = __float_as_int(v1.w);
        if (p0 < T0) {
            float4 o = sm[p0];
            v0.x += o.x; v0.y += o.y; v0.z += o.z; v0.w = o.w;
        }
        if (p1 < T0) {
            float4 o = sm[p1];
            v1.x += o.x; v1.y += o.y; v1.z += o.z; v1.w = o.w;
        }
        __syncthreads();
        sm[e0] = v0;
        sm[e1] = v1;
        __syncthreads();
    }

    float4* Fb = g_F + (size_t)tree * NN;
    for (int i = threadIdx.x; i < T0; i += blockDim.x) {
        float4 v = sm[i];
        Fb[i] = make_float4(v.x, v.y, v.z, 0.0f);
    }
}

// ---------------------------------------------------------------------------
// Kernel C (cascade): finalize F for nodes [start, end) of every tree.
// Everything below `start` is already final in g_F, so each node walks
// g_node only while p >= start (avg < 1 hop for 4x range steps), then
// adds the finalized ancestor value.
// grid: (blocks_for_range, NT)
// ---------------------------------------------------------------------------
__global__ void k_cascade(int start, int end) {
    const int tree = blockIdx.y;
    const int n = start + blockIdx.x * blockDim.x + threadIdx.x;
    if (n >= end) return;

    const float4* nb = g_node + (size_t)tree * NN;
    float4 v = nb[n];
    float ax = v.x, ay = v.y, az = v.z;
    int p = __float_as_int(v.w);

    while (p >= start) {
        float4 u = __ldg(&nb[p]);
        ax += u.x; ay += u.y; az += u.z;
        p = __float_as_int(u.w);
    }
    float4 f = __ldg(&g_F[(size_t)tree * NN + p]);
    g_F[(size_t)tree * NN + n] = make_float4(ax + f.x, ay + f.y, az + f.z, 0.0f);
}

// ---------------------------------------------------------------------------
// Kernel D: pixel gather. 4 pixels per thread; one 16B gather serves all
// 3 output channels; coalesced float4 stores per channel plane.
// Streaming hints keep g_F resident in L2 against the 192MB pix/out stream.
// ---------------------------------------------------------------------------
__global__ void k_gather(const int4* __restrict__ pix4,
                         float* __restrict__ out) {
    int t = blockIdx.x * blockDim.x + threadIdx.x;
    if (t >= NPIX / 4) return;

    const int q0   = 4 * t;              // first pixel (global)
    const int tree = q0 >> 20;           // HWPX = 2^20
    const int p    = q0 & (HWPX - 1);

    int4 nd = __ldcs(&pix4[t]);

    const float4* Fb = g_F + (size_t)tree * NN;
    float4 F0 = __ldg(&Fb[nd.x]);
    float4 F1 = __ldg(&Fb[nd.y]);
    float4 F2 = __ldg(&Fb[nd.z]);
    float4 F3 = __ldg(&Fb[nd.w]);

    float* o = out + (size_t)tree * 3 * HWPX + p;
    __stcs((float4*)(o),            make_float4(F0.x, F1.x, F2.x, F3.x));
    __stcs((float4*)(o + HWPX),     make_float4(F0.y, F1.y, F2.y, F3.y));
    __stcs((float4*)(o + 2 * HWPX), make_float4(F0.z, F1.z, F2.z, F3.z));
}

// ---------------------------------------------------------------------------
// Entry point
// Inputs: attrs, residue, W0, W1, W2, b0, b1, b2, parent, pixel_node
// ---------------------------------------------------------------------------
extern "C" void kernel_launch(void* const* d_in, const int* in_sizes, int n_in,
                              void* d_out, int out_size) {
    const float* attrs   = (const float*)d_in[0];
    const float* residue = (const float*)d_in[1];
    const float* W0      = (const float*)d_in[2];
    const float* W1      = (const float*)d_in[3];
    const float* W2      = (const float*)d_in[4];
    const float* b0      = (const float*)d_in[5];
    const float* b1      = (const float*)d_in[6];
    const float* b2      = (const float*)d_in[7];
    const int*   parent  = (const int*)d_in[8];
    const int*   pix     = (const int*)d_in[9];
    float*       out     = (float*)d_out;

    {
        int threads = 256;
        int blocks = (TOTAL / 4 + threads - 1) / threads;
        k_contrib<<<blocks, threads>>>((const float4*)attrs, (const float4*)residue,
                                       W0, W1, W2, b0, b1, b2, (const int4*)parent);
    }
    k_prefix<<<NT, 1024>>>();

    // Cascaded finalization: each stage walks only within its own range.
    const int stages[5] = {2048, 8192, 32768, 131072, 262144};
    for (int s = 0; s < 4; s++) {
        int start = stages[s], end = stages[s + 1];
        int threads = 256;
        dim3 grid((end - start + threads - 1) / threads, NT);
        k_cascade<<<grid, threads>>>(start, end);
    }

    {
        int threads = 256;
        int blocks = (NPIX / 4 + threads - 1) / threads;
        k_gather<<<blocks, threads>>>((const int4*)pix, out);
    }
}